// round 13
// baseline (speedup 1.0000x reference)
#include <cuda_runtime.h>
#include <cuda_bf16.h>

#define EPSF 1e-8f
#define LAMBDAF 1e-3f
#define LN2PI_HALF_F 0.91893853320467274178f

typedef unsigned long long u64;
typedef unsigned int u32;
__device__ __forceinline__ u64 f2pk(float lo, float hi){
    u64 r; asm("mov.b64 %0,{%1,%2};" : "=l"(r) : "f"(lo), "f"(hi)); return r;
}
__device__ __forceinline__ void f2up(u64 v, float& lo, float& hi){
    asm("mov.b64 {%0,%1},%2;" : "=f"(lo), "=f"(hi) : "l"(v));
}
__device__ __forceinline__ u64 ffma2(u64 a, u64 b, u64 c){
    u64 d; asm("fma.rn.f32x2 %0,%1,%2,%3;" : "=l"(d) : "l"(a), "l"(b), "l"(c)); return d;
}
__device__ __forceinline__ u64 fmul2(u64 a, u64 b){
    u64 d; asm("mul.rn.f32x2 %0,%1,%2;" : "=l"(d) : "l"(a), "l"(b)); return d;
}

// ---------------- network dims ----------------
#define NB 32
#define H0 64
#define H1 30
#define C1 64
#define B1 8
#define PS 16
#define H2 15
#define CC1_IN 8
#define CC1_OUT 16
#define H3 8
#define CC2_IN 16
#define CC2_OUT 16
#define CLS_D 16
#define CLS_E 10
#define CLS_BIN (H3*H3*CLS_D)   // 1024

// ---------------- scratch ----------------
__device__ float g_pose1[NB*H1*H1*B1*PS];
__device__ float g_a1   [NB*H1*H1*B1];
__device__ float g_pose2[NB*H2*H2*B1*PS];
__device__ float g_a2   [NB*H2*H2*B1];
__device__ float g_pose3[NB*H2*H2*CC1_OUT*PS];
__device__ float g_a3   [NB*H2*H2*CC1_OUT];
__device__ float g_pose4[NB*H3*H3*CC1_OUT*PS];
__device__ float g_a4   [NB*H3*H3*CC1_OUT];
__device__ float g_pose5[NB*H3*H3*CC2_OUT*PS];
__device__ float g_a5   [NB*H3*H3*CC2_OUT];
__device__ float g_votes[NB*CLS_E*CLS_BIN*PS];
__device__ float g_r    [NB*CLS_E*CLS_BIN];
__device__ float g_S    [NB*CLS_E*2*33];
__device__ float g_mu   [NB*CLS_E*16];
__device__ float g_i2   [NB*CLS_E*16];
__device__ float g_cst  [NB*CLS_E];

__device__ __forceinline__ float sigmoidf_(float x){ return 1.0f/(1.0f+expf(-x)); }

// ---------------- 1+2 fused: conv stem + relu + primary caps (f32x2) ----------------
#define CP_SMEM_FLOATS (448 + 3900 + 1600 + 8192 + 512 + 128 + 8 + 64)
__global__ void __launch_bounds__(256) convprim_kernel(
    const float* __restrict__ x,  const float* __restrict__ wc,
    const float* __restrict__ bc,
    const float* __restrict__ Wp, const float* __restrict__ bp,
    const float* __restrict__ Wa, const float* __restrict__ ba)
{
    extern __shared__ float sm[];
    float* sx  = sm;
    float* sy  = sx  + 448;
    float* swc = sy  + 3900;
    float* sWp = swc + 1600;
    float* sWa = sWp + 8192;
    float* sbp = sWa + 512;
    float* sba = sbp + 128;
    float* sbc = sba + 8;

    int tid = threadIdx.x;
    int blk = blockIdx.x;
    int ry = blk % 15, b = blk / 15;

    for (int i=tid;i<1600;i+=256) swc[i]=wc[i];
    for (int i=tid;i<8192;i+=256) sWp[i]=Wp[i];
    for (int i=tid;i<512; i+=256) sWa[i]=Wa[i];
    if (tid<128) sbp[tid]=bp[tid];
    if (tid<8)   sba[tid]=ba[tid];
    if (tid<64)  sbc[tid]=bc[tid];
    const float* xb = x + (size_t)b*H0*H0;
    for (int i=tid;i<7*64;i+=256){
        int r=i>>6, cx=i&63;
        sx[i] = xb[(4*ry+r)*H0 + cx];
    }
    __syncthreads();

    for (int i=tid;i<60*16;i+=256){
        int c4 = (i & 15)*4, pos = i >> 4;
        int oy_l = pos/30, ox = pos%30;
        u64 a0 = f2pk(sbc[c4],   sbc[c4+1]);
        u64 a1 = f2pk(sbc[c4+2], sbc[c4+3]);
        #pragma unroll
        for (int kh=0;kh<5;kh++){
            const float* xr = &sx[(oy_l*2+kh)*64 + ox*2];
            #pragma unroll
            for (int kw=0;kw<5;kw++){
                float xv = xr[kw];
                u64 x2 = f2pk(xv,xv);
                const u64* w2 = (const u64*)&swc[(kh*5+kw)*64 + c4];
                a0 = ffma2(x2, w2[0], a0);
                a1 = ffma2(x2, w2[1], a1);
            }
        }
        float v0,v1,v2,v3;
        f2up(a0,v0,v1); f2up(a1,v2,v3);
        float* yo = &sy[pos*65 + c4];
        yo[0]=fmaxf(v0,0.f); yo[1]=fmaxf(v1,0.f);
        yo[2]=fmaxf(v2,0.f); yo[3]=fmaxf(v3,0.f);
    }
    __syncthreads();

    for (int i=tid;i<60*34;i+=256){
        int qd = i % 34, pos = i / 34;
        int oy = ry*2 + pos/30, ox = pos%30;
        size_t pg = ((size_t)(b*H1+oy))*H1 + ox;
        const float* yy = &sy[pos*65];
        if (qd < 32){
            int d0 = qd*4;
            u64 a0 = f2pk(sbp[d0],   sbp[d0+1]);
            u64 a1 = f2pk(sbp[d0+2], sbp[d0+3]);
            #pragma unroll 8
            for (int c=0;c<64;c++){
                float yv = yy[c];
                u64 y2 = f2pk(yv,yv);
                const u64* w2 = (const u64*)&sWp[c*128 + d0];
                a0 = ffma2(y2, w2[0], a0);
                a1 = ffma2(y2, w2[1], a1);
            }
            float v0,v1,v2,v3;
            f2up(a0,v0,v1); f2up(a1,v2,v3);
            float4 o4; o4.x=v0; o4.y=v1; o4.z=v2; o4.w=v3;
            *(float4*)&g_pose1[pg*128 + d0] = o4;
        } else {
            int da0 = (qd-32)*4;
            u64 a0 = f2pk(sba[da0],   sba[da0+1]);
            u64 a1 = f2pk(sba[da0+2], sba[da0+3]);
            #pragma unroll 8
            for (int c=0;c<64;c++){
                float yv = yy[c];
                u64 y2 = f2pk(yv,yv);
                const u64* w2 = (const u64*)&sWa[c*8 + da0];
                a0 = ffma2(y2, w2[0], a0);
                a1 = ffma2(y2, w2[1], a1);
            }
            float v0,v1,v2,v3;
            f2up(a0,v0,v1); f2up(a1,v2,v3);
            float4 o4;
            o4.x=sigmoidf_(v0); o4.y=sigmoidf_(v1);
            o4.z=sigmoidf_(v2); o4.w=sigmoidf_(v3);
            *(float4*)&g_a1[pg*8 + da0] = o4;
        }
    }
}

// ---------------- dw caps HALF-split, BRANCHLESS padded plane (dw1) ----------------
template<int K, int PAD, int HIN, int HOUT, int BC, int OYT, int BLK>
__global__ void __launch_bounds__(BLK) dw_half_kernel(
    const float* __restrict__ pose_in,
    const float* __restrict__ a_in_g,
    const float* __restrict__ W,
    const float* __restrict__ bu, const float* __restrict__ ba,
    float* __restrict__ pose_out,
    float* __restrict__ a_out_g)
{
    constexpr int NT    = (HOUT + OYT - 1)/OYT;
    constexpr int IROWS = (OYT-1)*2 + K;
    constexpr int HINP  = HIN + 2*PAD;
    constexpr int PLANE = IROWS*HINP;
    constexpr int NPOS  = OYT*HOUT;
    constexpr int WSOFF = ((17*PLANE) + 1) & ~1;   // EVEN float offset => 8B-aligned ws
    extern __shared__ float dsm[];
    float* ps  = dsm;                 // [16][PLANE]
    float* as  = ps + 16*PLANE;       // [PLANE]
    float* ws  = dsm + WSOFF;         // [K*K*16], 8B-aligned
    float* s_h = ws + K*K*16;         // [NPOS]

    int blk = blockIdx.x;
    int tile = blk % NT;
    int c    = (blk / NT) % BC;
    int b    = blk / (NT*BC);
    int oy0  = tile*OYT;
    int iy0  = oy0*2 - PAD;
    int tid  = threadIdx.x;

    for (int i=tid; i<K*K*16; i+=BLK)
        ws[i] = W[(i>>4)*(BC*16) + c*16 + (i&15)];

    const float4* pbase = (const float4*)pose_in;
    for (int i=tid; i<PLANE*4; i+=BLK){
        int q4 = i & 3;
        int pos = i >> 2;
        int r = pos / HINP, col = pos % HINP;
        int iy = iy0 + r;
        int ix = col - PAD;
        float4 v = make_float4(0.f,0.f,0.f,0.f);
        bool ok = (iy >= 0 && iy < HIN && ix >= 0 && ix < HIN);
        if (ok)
            v = pbase[((size_t)((b*HIN+iy)*HIN+ix))*(BC*4) + c*4 + q4];
        ps[(q4*4+0)*PLANE+pos]=v.x; ps[(q4*4+1)*PLANE+pos]=v.y;
        ps[(q4*4+2)*PLANE+pos]=v.z; ps[(q4*4+3)*PLANE+pos]=v.w;
        if (q4 == 0)
            as[pos] = ok ? a_in_g[((b*HIN+iy)*HIN+ix)*BC + c] : 0.0f;
    }
    __syncthreads();

    bool act = tid < 2*NPOS;
    int half = 0, pos_t = 0, oy = 0, ox = 0, oy_l = 0;
    if (act){
        half  = (tid >= NPOS) ? 1 : 0;
        pos_t = tid - half*NPOS;
        oy_l = pos_t / HOUT;
        ox = pos_t % HOUT;
        oy = oy0 + oy_l;
        if (oy >= HOUT) act = false;
    }

    float S0 = 0.0f;
    u64 T1p[4], T2p[4];
    #pragma unroll
    for (int a=0;a<4;a++){ T1p[a]=f2pk(0.f,0.f); T2p[a]=f2pk(0.f,0.f); }

    if (act){
        int base = oy_l*2*HINP + ox*2;
        #pragma unroll
        for (int ki=0; ki<K; ki++){
            #pragma unroll
            for (int kj=0; kj<K; kj++){
                int sp = base + ki*HINP + kj;
                float w = as[sp];
                S0 += w;
                u64 wp = f2pk(w,w);
                const u64* wk2 = (const u64*)&ws[(ki*K+kj)*16];
                #pragma unroll
                for (int ii=0; ii<2; ii++){
                    int irow = half*2 + ii;
                    u64 pm2[4];
                    #pragma unroll
                    for (int j=0;j<4;j++){
                        float pj = ps[(irow*4+j)*PLANE + sp];
                        pm2[j] = f2pk(pj,pj);
                    }
                    #pragma unroll
                    for (int l2=0;l2<2;l2++){
                        u64 vv = f2pk(0.f,0.f);
                        #pragma unroll
                        for (int j=0;j<4;j++)
                            vv = ffma2(pm2[j], wk2[j*2+l2], vv);
                        int a = ii*2 + l2;
                        T1p[a] = ffma2(wp, vv, T1p[a]);
                        T2p[a] = ffma2(fmul2(wp, vv), vv, T2p[a]);
                    }
                }
            }
        }
    }

    float hls_own = 0.0f;
    if (act){
        float inv = 1.0f/(S0 + EPSF);
        float mu[8];
        #pragma unroll
        for (int a=0;a<4;a++){
            float t1l,t1h,t2l,t2h;
            f2up(T1p[a],t1l,t1h); f2up(T2p[a],t2l,t2h);
            int ii = a>>1, l2 = a&1;
            int q0 = ii*4 + l2*2;
            float m0 = t1l*inv;
            float m1 = t1h*inv;
            mu[q0]   = m0;
            mu[q0+1] = m1;
            float sg0 = fmaxf((t2l - 2.0f*m0*t1l + m0*m0*S0)*inv, 0.0f) + EPSF;
            float sg1 = fmaxf((t2h - 2.0f*m1*t1h + m1*m1*S0)*inv, 0.0f) + EPSF;
            hls_own += 0.5f*logf(sg0) + 0.5f*logf(sg1);
        }
        size_t o = (size_t)((b*HOUT+oy)*HOUT+ox);
        float4* po = (float4*)&pose_out[o*(BC*16) + c*16 + half*8];
        float4 v4;
        v4.x=mu[0]; v4.y=mu[1]; v4.z=mu[2]; v4.w=mu[3]; po[0]=v4;
        v4.x=mu[4]; v4.y=mu[5]; v4.z=mu[6]; v4.w=mu[7]; po[1]=v4;
        if (half) s_h[pos_t] = hls_own;
    }
    __syncthreads();
    if (act && half == 0){
        float hls = hls_own + s_h[pos_t];
        float cost = (hls + 16.0f*bu[0]) * S0;
        float ao = sigmoidf_(LAMBDAF*(ba[0] - cost));
        size_t o = (size_t)((b*HOUT+oy)*HOUT+ox);
        a_out_g[o*BC + c] = ao;
    }
}

// ---------------- dw caps QUARTER-split, BRANCHLESS padded plane (dw2) ----------------
template<int K, int PAD, int HIN, int HOUT, int BC, int OYT, int BLK>
__global__ void __launch_bounds__(BLK) dw_quarter_kernel(
    const float* __restrict__ pose_in,
    const float* __restrict__ a_in_g,
    const float* __restrict__ W,
    const float* __restrict__ bu, const float* __restrict__ ba,
    float* __restrict__ pose_out,
    float* __restrict__ a_out_g)
{
    constexpr int NT    = (HOUT + OYT - 1)/OYT;
    constexpr int IROWS = (OYT-1)*2 + K;
    constexpr int HINP  = HIN + 2*PAD;
    constexpr int PLANE = IROWS*HINP;
    constexpr int NPOS  = OYT*HOUT;
    constexpr int WSOFF = ((17*PLANE) + 1) & ~1;   // EVEN float offset => 8B-aligned ws
    extern __shared__ float dsm[];
    float* ps  = dsm;                 // [16][PLANE]
    float* as  = ps + 16*PLANE;       // [PLANE]
    float* ws  = dsm + WSOFF;         // [K*K*16], 8B-aligned
    float* s_h = ws + K*K*16;         // [4][NPOS]

    int blk = blockIdx.x;
    int tile = blk % NT;
    int c    = (blk / NT) % BC;
    int b    = blk / (NT*BC);
    int oy0  = tile*OYT;
    int iy0  = oy0*2 - PAD;
    int tid  = threadIdx.x;

    for (int i=tid; i<K*K*16; i+=BLK)
        ws[i] = W[(i>>4)*(BC*16) + c*16 + (i&15)];

    const float4* pbase = (const float4*)pose_in;
    for (int i=tid; i<PLANE*4; i+=BLK){
        int q4 = i & 3;
        int pos = i >> 2;
        int r = pos / HINP, col = pos % HINP;
        int iy = iy0 + r;
        int ix = col - PAD;
        float4 v = make_float4(0.f,0.f,0.f,0.f);
        bool ok = (iy >= 0 && iy < HIN && ix >= 0 && ix < HIN);
        if (ok)
            v = pbase[((size_t)((b*HIN+iy)*HIN+ix))*(BC*4) + c*4 + q4];
        ps[(q4*4+0)*PLANE+pos]=v.x; ps[(q4*4+1)*PLANE+pos]=v.y;
        ps[(q4*4+2)*PLANE+pos]=v.z; ps[(q4*4+3)*PLANE+pos]=v.w;
        if (q4 == 0)
            as[pos] = ok ? a_in_g[((b*HIN+iy)*HIN+ix)*BC + c] : 0.0f;
    }
    __syncthreads();

    bool act = tid < 4*NPOS;
    int quarter = 0, pos_t = 0, oy = 0, ox = 0, oy_l = 0;
    if (act){
        quarter = tid / NPOS;
        pos_t   = tid - quarter*NPOS;
        oy_l = pos_t / HOUT;
        ox = pos_t % HOUT;
        oy = oy0 + oy_l;
        if (oy >= HOUT) act = false;
    }

    float S0 = 0.0f;
    u64 T1p[2], T2p[2];
    T1p[0]=f2pk(0.f,0.f); T1p[1]=f2pk(0.f,0.f);
    T2p[0]=f2pk(0.f,0.f); T2p[1]=f2pk(0.f,0.f);

    if (act){
        int base = oy_l*2*HINP + ox*2;
        #pragma unroll
        for (int ki=0; ki<K; ki++){
            #pragma unroll
            for (int kj=0; kj<K; kj++){
                int sp = base + ki*HINP + kj;
                float w = as[sp];
                S0 += w;
                u64 wp = f2pk(w,w);
                const u64* wk2 = (const u64*)&ws[(ki*K+kj)*16];
                u64 pm2[4];
                #pragma unroll
                for (int j=0;j<4;j++){
                    float pj = ps[(quarter*4+j)*PLANE + sp];
                    pm2[j] = f2pk(pj,pj);
                }
                #pragma unroll
                for (int l2=0;l2<2;l2++){
                    u64 vv = f2pk(0.f,0.f);
                    #pragma unroll
                    for (int j=0;j<4;j++)
                        vv = ffma2(pm2[j], wk2[j*2+l2], vv);
                    T1p[l2] = ffma2(wp, vv, T1p[l2]);
                    T2p[l2] = ffma2(fmul2(wp, vv), vv, T2p[l2]);
                }
            }
        }
    }

    float hls_own = 0.0f;
    if (act){
        float inv = 1.0f/(S0 + EPSF);
        float mu[4];
        #pragma unroll
        for (int l2=0;l2<2;l2++){
            float t1l,t1h,t2l,t2h;
            f2up(T1p[l2],t1l,t1h); f2up(T2p[l2],t2l,t2h);
            float m0 = t1l*inv;
            float m1 = t1h*inv;
            mu[l2*2]   = m0;
            mu[l2*2+1] = m1;
            float sg0 = fmaxf((t2l - 2.0f*m0*t1l + m0*m0*S0)*inv, 0.0f) + EPSF;
            float sg1 = fmaxf((t2h - 2.0f*m1*t1h + m1*m1*S0)*inv, 0.0f) + EPSF;
            hls_own += 0.5f*logf(sg0) + 0.5f*logf(sg1);
        }
        size_t o = (size_t)((b*HOUT+oy)*HOUT+ox);
        float4 v4; v4.x=mu[0]; v4.y=mu[1]; v4.z=mu[2]; v4.w=mu[3];
        *(float4*)&pose_out[o*(BC*16) + c*16 + quarter*4] = v4;
        s_h[quarter*NPOS + pos_t] = hls_own;
    }
    __syncthreads();
    if (act && quarter == 0){
        float hls = hls_own + s_h[NPOS+pos_t] + s_h[2*NPOS+pos_t] + s_h[3*NPOS+pos_t];
        float cost = (hls + 16.0f*bu[0]) * S0;
        float ao = sigmoidf_(LAMBDAF*(ba[0] - cost));
        size_t o = (size_t)((b*HOUT+oy)*HOUT+ox);
        a_out_g[o*BC + c] = ao;
    }
}

// ---------------- 1x1 conv caps: warp-per-position, float4-vectorized smem votes ----------------
template<int BIN, int WPB>
__global__ void __launch_bounds__(WPB*32) cc_warp_kernel(
    const float* __restrict__ pose_in,
    const float* __restrict__ a_g,
    const float* __restrict__ W,
    const float* __restrict__ bu, const float* __restrict__ ba,
    float* __restrict__ pose_out,
    float* __restrict__ a_out_g,
    int npos)
{
    __shared__ float sW[BIN*256];
    __shared__ float4 sv[WPB][BIN*2*32];
    __shared__ float s_ln[WPB][BIN*17];
    __shared__ float s_rw[WPB][BIN*17];
    __shared__ float s_ain[WPB][BIN];

    int tid = threadIdx.x;
    for (int i=tid; i<BIN*256; i+=WPB*32){
        int c2 = i & 15; int rest = i >> 4;
        int l = rest & 3; int j = (rest>>2)&3; int bin = rest>>4;
        sW[i] = W[(((size_t)bin*16 + c2)*4 + j)*4 + l];
    }
    __syncthreads();

    int warp = tid >> 5, lane = tid & 31;
    int pos = blockIdx.x*WPB + warp;
    if (pos >= npos) return;
    int c = lane & 15, half = lane >> 4;
    float4* v  = sv[warp];
    float* lnp = s_ln[warp];
    float* rwp = s_rw[warp];
    float* ain = s_ain[warp];

    const float* pm = pose_in + (size_t)pos*BIN*16;
    const float* ag = a_g + (size_t)pos*BIN;
    if (half == 0 && c < BIN) ain[c] = ag[c];

    float T1[8], T2[8]; float S0 = 0.0f;
    #pragma unroll
    for (int q=0;q<8;q++){ T1[q]=0.0f; T2[q]=0.0f; }

    #pragma unroll
    for (int bin=0; bin<BIN; bin++){
        float w = ag[bin] * (1.0f/16.0f);
        S0 += w;
        const float4* pm4 = (const float4*)(pm + bin*16 + half*8);
        float4 p0 = pm4[0], p1 = pm4[1];
        float pmr[8] = {p0.x,p0.y,p0.z,p0.w,p1.x,p1.y,p1.z,p1.w};
        float sq[8];
        #pragma unroll
        for (int q=0;q<8;q++){
            int i0 = q>>2, l = q&3;
            float s = 0.0f;
            #pragma unroll
            for (int j=0;j<4;j++)
                s += pmr[i0*4+j] * sW[(((bin*4+j)*4+l)<<4) + c];
            sq[q] = s;
            T1[q] += w*s;
            T2[q] += w*s*s;
        }
        float4 v4a; v4a.x=sq[0]; v4a.y=sq[1]; v4a.z=sq[2]; v4a.w=sq[3];
        float4 v4b; v4b.x=sq[4]; v4b.y=sq[5]; v4b.z=sq[6]; v4b.w=sq[7];
        v[(bin*2+0)*32 + lane] = v4a;
        v[(bin*2+1)*32 + lane] = v4b;
    }

    float buC = bu[c], baC = ba[c];
    float mu[8], i2[8], cst = 0.0f, ao = 0.0f;
    {
        float inv = 1.0f/(S0 + EPSF);
        float hls = 0.0f;
        #pragma unroll
        for (int q=0;q<8;q++){
            float m = T1[q]*inv;
            mu[q] = m;
            float sg = fmaxf(T2[q]*inv - m*m, 0.0f) + EPSF;
            i2[q] = 0.5f/sg;
            hls += 0.5f*logf(sg);
        }
        hls += __shfl_xor_sync(0xffffffffu, hls, 16);
        float cost = (hls + 16.0f*buC) * S0;
        ao = sigmoidf_(LAMBDAF*(baC - cost));
        cst = -hls - 16.0f*LN2PI_HALF_F + logf(EPSF + ao);
    }

    #pragma unroll
    for (int it=0; it<2; it++){
        float part[BIN];
        #pragma unroll
        for (int bin=0;bin<BIN;bin++){
            float4 va = v[(bin*2+0)*32 + lane];
            float4 vb = v[(bin*2+1)*32 + lane];
            float d0=va.x-mu[0], d1=va.y-mu[1], d2=va.z-mu[2], d3=va.w-mu[3];
            float d4=vb.x-mu[4], d5=vb.y-mu[5], d6=vb.z-mu[6], d7=vb.w-mu[7];
            part[bin] = -(d0*d0*i2[0]+d1*d1*i2[1]+d2*d2*i2[2]+d3*d3*i2[3]
                        + d4*d4*i2[4]+d5*d5*i2[5]+d6*d6*i2[6]+d7*d7*i2[7]);
        }
        #pragma unroll
        for (int bin=0;bin<BIN;bin++)
            part[bin] += __shfl_xor_sync(0xffffffffu, part[bin], 16);
        if (half == 0){
            #pragma unroll
            for (int bin=0;bin<BIN;bin++)
                lnp[bin*17 + c] = part[bin] + cst;
        }
        __syncwarp();
        if (lane < BIN){
            float l16[16];
            float mx = -1e30f;
            #pragma unroll
            for (int c2=0;c2<16;c2++){ l16[c2] = lnp[lane*17 + c2]; mx = fmaxf(mx, l16[c2]); }
            float sum = 0.0f;
            #pragma unroll
            for (int c2=0;c2<16;c2++){ l16[c2] = expf(l16[c2]-mx); sum += l16[c2]; }
            float f = ain[lane]/sum;
            #pragma unroll
            for (int c2=0;c2<16;c2++) rwp[lane*17 + c2] = l16[c2]*f;
        }
        __syncwarp();
        float nT1[8], nT2[8]; float nS0 = 0.0f;
        #pragma unroll
        for (int q=0;q<8;q++){ nT1[q]=0.0f; nT2[q]=0.0f; }
        #pragma unroll
        for (int bin=0;bin<BIN;bin++){
            float w = rwp[bin*17 + c];
            nS0 += w;
            float4 va = v[(bin*2+0)*32 + lane];
            float4 vb = v[(bin*2+1)*32 + lane];
            nT1[0]+=w*va.x; nT2[0]+=w*va.x*va.x;
            nT1[1]+=w*va.y; nT2[1]+=w*va.y*va.y;
            nT1[2]+=w*va.z; nT2[2]+=w*va.z*va.z;
            nT1[3]+=w*va.w; nT2[3]+=w*va.w*va.w;
            nT1[4]+=w*vb.x; nT2[4]+=w*vb.x*vb.x;
            nT1[5]+=w*vb.y; nT2[5]+=w*vb.y*vb.y;
            nT1[6]+=w*vb.z; nT2[6]+=w*vb.z*vb.z;
            nT1[7]+=w*vb.w; nT2[7]+=w*vb.w*vb.w;
        }
        float inv = 1.0f/(nS0 + EPSF);
        float hls = 0.0f;
        #pragma unroll
        for (int q=0;q<8;q++){
            float m = nT1[q]*inv;
            mu[q] = m;
            float sg = fmaxf(nT2[q]*inv - m*m, 0.0f) + EPSF;
            i2[q] = 0.5f/sg;
            hls += 0.5f*logf(sg);
        }
        hls += __shfl_xor_sync(0xffffffffu, hls, 16);
        float cost = (hls + 16.0f*buC) * nS0;
        ao = sigmoidf_(LAMBDAF*(baC - cost));
        if (it == 0) cst = -hls - 16.0f*LN2PI_HALF_F + logf(EPSF + ao);
    }

    size_t ob = (size_t)pos*256 + c*16 + half*8;
    #pragma unroll
    for (int q=0;q<8;q++) pose_out[ob+q] = mu[q];
    if (half == 0) a_out_g[(size_t)pos*16 + c] = ao;
}

// ---------------- cls iter0: votes + split partial sums (grid NB*CLS_E*2) ----------------
__global__ void __launch_bounds__(256) cls_vred2_kernel(const float* __restrict__ W)
{
    int be2 = blockIdx.x;
    int halfb = be2 & 1;
    int be = be2 >> 1;
    int b = be / CLS_E, e = be % CLS_E;
    int tid = threadIdx.x, lane = tid & 31, warp = tid >> 5;

    __shared__ float sw[16*17];
    if (tid < 256){
        int d = tid >> 4, p = tid & 15;
        int j = p >> 2, l = p & 3;
        sw[d*17 + p] = W[((d*CLS_E + e)*4 + j)*4 + l];
    }
    __syncthreads();

    float s0 = 0.0f, s1[16], s2[16];
    #pragma unroll
    for (int q=0;q<16;q++){ s1[q]=0.0f; s2[q]=0.0f; }

    int bin0 = halfb*512;
    for (int bin=bin0+tid; bin<bin0+512; bin+=256){
        int d  = bin & 15;
        int ww = (bin >> 4) & 7;
        int hh = bin >> 7;
        const float4* pm4 = (const float4*)(g_pose5 + ((size_t)b*CLS_BIN + bin)*16);
        float4 P0 = pm4[0], P1 = pm4[1], P2 = pm4[2], P3 = pm4[3];
        float pmv[16] = {P0.x,P0.y,P0.z,P0.w, P1.x,P1.y,P1.z,P1.w,
                         P2.x,P2.y,P2.z,P2.w, P3.x,P3.y,P3.z,P3.w};
        float w = 0.1f * g_a5[(size_t)b*CLS_BIN + bin];
        s0 += w;
        float4* vout = (float4*)(g_votes + ((size_t)be*CLS_BIN + bin)*16);
        const float* swd = &sw[d*17];
        #pragma unroll
        for (int i=0;i<4;i++){
            float vv[4];
            #pragma unroll
            for (int l=0;l<4;l++){
                float s = 0.0f;
                #pragma unroll
                for (int j=0;j<4;j++) s += pmv[i*4+j]*swd[j*4+l];
                vv[l] = s;
            }
            if (i == 0){ vv[0] += (float)hh*0.125f; vv[1] += (float)ww*0.125f; }
            float4 o4; o4.x=vv[0]; o4.y=vv[1]; o4.z=vv[2]; o4.w=vv[3];
            vout[i] = o4;
            #pragma unroll
            for (int l=0;l<4;l++){
                s1[i*4+l] += w*vv[l];
                s2[i*4+l] += w*vv[l]*vv[l];
            }
        }
    }

    #pragma unroll
    for (int off=16; off; off>>=1){
        s0 += __shfl_xor_sync(0xffffffffu, s0, off);
        #pragma unroll
        for (int q=0;q<16;q++){
            s1[q] += __shfl_xor_sync(0xffffffffu, s1[q], off);
            s2[q] += __shfl_xor_sync(0xffffffffu, s2[q], off);
        }
    }
    __shared__ float red[8][33];
    if (lane == 0){
        red[warp][0] = s0;
        #pragma unroll
        for (int q=0;q<16;q++){ red[warp][1+q]=s1[q]; red[warp][17+q]=s2[q]; }
    }
    __syncthreads();
    if (tid < 33){
        float t = 0.0f;
        #pragma unroll
        for (int w8=0;w8<8;w8++) t += red[w8][tid];
        g_S[((size_t)be*2 + halfb)*33 + tid] = t;
    }
}

// ---------------- cls M-step: split partial sums from stored votes+r ----------------
__global__ void __launch_bounds__(256) cls_mstep2_kernel()
{
    int be2 = blockIdx.x;
    int halfb = be2 & 1;
    int be = be2 >> 1;
    int b = be / CLS_E;
    const float* vb = g_votes + (size_t)be*CLS_BIN*16;
    const float* rr = g_r + (size_t)be*CLS_BIN;
    const float* ab = g_a5 + (size_t)b*CLS_BIN;
    int tid = threadIdx.x, lane = tid & 31, warp = tid >> 5;

    float s0 = 0.0f, s1[16], s2[16];
    #pragma unroll
    for (int q=0;q<16;q++){ s1[q]=0.0f; s2[q]=0.0f; }

    int bin0 = halfb*512;
    for (int bin=bin0+tid; bin<bin0+512; bin+=256){
        float w = rr[bin] * ab[bin];
        s0 += w;
        const float4* vv = (const float4*)(vb + (size_t)bin*16);
        #pragma unroll
        for (int q4=0;q4<4;q4++){
            float4 v4 = vv[q4];
            s1[q4*4+0] += w*v4.x; s2[q4*4+0] += w*v4.x*v4.x;
            s1[q4*4+1] += w*v4.y; s2[q4*4+1] += w*v4.y*v4.y;
            s1[q4*4+2] += w*v4.z; s2[q4*4+2] += w*v4.z*v4.z;
            s1[q4*4+3] += w*v4.w; s2[q4*4+3] += w*v4.w*v4.w;
        }
    }
    #pragma unroll
    for (int off=16; off; off>>=1){
        s0 += __shfl_xor_sync(0xffffffffu, s0, off);
        #pragma unroll
        for (int q=0;q<16;q++){
            s1[q] += __shfl_xor_sync(0xffffffffu, s1[q], off);
            s2[q] += __shfl_xor_sync(0xffffffffu, s2[q], off);
        }
    }
    __shared__ float red[8][33];
    if (lane == 0){
        red[warp][0] = s0;
        #pragma unroll
        for (int q=0;q<16;q++){ red[warp][1+q]=s1[q]; red[warp][17+q]=s2[q]; }
    }
    __syncthreads();
    if (tid < 33){
        float t = 0.0f;
        #pragma unroll
        for (int w8=0;w8<8;w8++) t += red[w8][tid];
        g_S[((size_t)be*2 + halfb)*33 + tid] = t;
    }
}

// ---------------- cls E-step: finalize-in-preamble + softmax (grid NB*4) ----------------
__global__ void __launch_bounds__(256) cls_estep2_kernel(
    const float* __restrict__ bu, const float* __restrict__ ba)
{
    __shared__ float s_mu[CLS_E*16];
    __shared__ float s_i2[CLS_E*16];
    __shared__ float s_cst[CLS_E];

    int tid = threadIdx.x;
    int b = blockIdx.x >> 2;
    int bin = ((blockIdx.x & 3) << 8) + tid;

    if (tid < 160){
        int e = tid >> 4, q = tid & 15;
        size_t base = ((size_t)(b*CLS_E + e))*66;
        float S0 = g_S[base] + g_S[base+33];
        float S1 = g_S[base+1+q]  + g_S[base+34+q];
        float S2 = g_S[base+17+q] + g_S[base+50+q];
        float inv = 1.0f/(S0 + EPSF);
        float m = S1*inv;
        float sg = fmaxf((S2 - 2.0f*m*S1 + m*m*S0)*inv, 0.0f) + EPSF;
        s_mu[tid] = m;
        s_i2[tid] = 0.5f/sg;
        float hl = 0.5f*logf(sg);
        #pragma unroll
        for (int off=8; off; off>>=1)
            hl += __shfl_xor_sync(0xffffffffu, hl, off);
        if (q == 0){
            float cost = (hl + 16.0f*bu[e]) * S0;
            float ao = sigmoidf_(LAMBDAF*(ba[e] - cost));
            s_cst[e] = -hl - 16.0f*LN2PI_HALF_F + logf(EPSF + ao);
        }
    }
    __syncthreads();

    float lnap[CLS_E];
    float mx = -1e30f;
    #pragma unroll
    for (int e=0;e<CLS_E;e++){
        int be = b*CLS_E + e;
        const float4* vv = (const float4*)(g_votes + ((size_t)be*CLS_BIN + bin)*16);
        const float4* mm = (const float4*)&s_mu[e*16];
        const float4* ii = (const float4*)&s_i2[e*16];
        float acc = 0.0f;
        #pragma unroll
        for (int q4=0;q4<4;q4++){
            float4 v4 = vv[q4], m4 = mm[q4], i4 = ii[q4];
            float d0=v4.x-m4.x, d1=v4.y-m4.y, d2=v4.z-m4.z, d3=v4.w-m4.w;
            acc -= d0*d0*i4.x + d1*d1*i4.y + d2*d2*i4.z + d3*d3*i4.w;
        }
        lnap[e] = acc + s_cst[e];
        mx = fmaxf(mx, lnap[e]);
    }
    float sum = 0.0f;
    #pragma unroll
    for (int e=0;e<CLS_E;e++){ lnap[e] = expf(lnap[e]-mx); sum += lnap[e]; }
    float isum = 1.0f/sum;
    #pragma unroll
    for (int e=0;e<CLS_E;e++)
        g_r[((size_t)(b*CLS_E+e))*CLS_BIN + bin] = lnap[e]*isum;
}

// ---------------- cls final M-step: full reduce + a_out (grid NB*CLS_E) ----------------
__global__ void __launch_bounds__(256) cls_redfin_last_kernel(
    const float* __restrict__ bu, const float* __restrict__ ba,
    float* __restrict__ out)
{
    int be = blockIdx.x;
    int b = be / CLS_E, e = be % CLS_E;
    const float* vb = g_votes + (size_t)be*CLS_BIN*16;
    const float* rr = g_r + (size_t)be*CLS_BIN;
    const float* ab = g_a5 + (size_t)b*CLS_BIN;
    int tid = threadIdx.x, lane = tid & 31, warp = tid >> 5;

    float s0 = 0.0f, s1[16], s2[16];
    #pragma unroll
    for (int q=0;q<16;q++){ s1[q]=0.0f; s2[q]=0.0f; }

    for (int bin=tid; bin<CLS_BIN; bin+=256){
        float w = rr[bin] * ab[bin];
        s0 += w;
        const float4* vv = (const float4*)(vb + (size_t)bin*16);
        #pragma unroll
        for (int q4=0;q4<4;q4++){
            float4 v4 = vv[q4];
            s1[q4*4+0] += w*v4.x; s2[q4*4+0] += w*v4.x*v4.x;
            s1[q4*4+1] += w*v4.y; s2[q4*4+1] += w*v4.y*v4.y;
            s1[q4*4+2] += w*v4.z; s2[q4*4+2] += w*v4.z*v4.z;
            s1[q4*4+3] += w*v4.w; s2[q4*4+3] += w*v4.w*v4.w;
        }
    }
    #pragma unroll
    for (int off=16; off; off>>=1){
        s0 += __shfl_xor_sync(0xffffffffu, s0, off);
        #pragma unroll
        for (int q=0;q<16;q++){
            s1[q] += __shfl_xor_sync(0xffffffffu, s1[q], off);
            s2[q] += __shfl_xor_sync(0xffffffffu, s2[q], off);
        }
    }
    __shared__ float red[8][33];
    __shared__ float smS[33];
    if (lane == 0){
        red[warp][0] = s0;
        #pragma unroll
        for (int q=0;q<16;q++){ red[warp][1+q]=s1[q]; red[warp][17+q]=s2[q]; }
    }
    __syncthreads();
    if (tid < 33){
        float t = 0.0f;
        #pragma unroll
        for (int w8=0;w8<8;w8++) t += red[w8][tid];
        smS[tid] = t;
    }
    __syncthreads();
    if (tid < 16){
        float S0 = smS[0];
        float S1 = smS[1+tid];
        float S2 = smS[17+tid];
        float inv = 1.0f/(S0 + EPSF);
        float m = S1*inv;
        float sg = fmaxf((S2 - 2.0f*m*S1 + m*m*S0)*inv, 0.0f) + EPSF;
        float hl = 0.5f*logf(sg);
        #pragma unroll
        for (int off=8; off; off>>=1)
            hl += __shfl_xor_sync(0x0000ffffu, hl, off);
        if (tid == 0){
            float cost = (hl + 16.0f*bu[e]) * S0;
            float ao = sigmoidf_(LAMBDAF*(ba[e] - cost));
            out[b*CLS_E + e] = ao;
        }
    }
}

// ---------------- launch ----------------
extern "C" void kernel_launch(void* const* d_in, const int* in_sizes, int n_in,
                              void* d_out, int out_size)
{
    const float* x       = (const float*)d_in[0];
    const float* conv1_w = (const float*)d_in[1];
    const float* conv1_b = (const float*)d_in[2];
    const float* ppw     = (const float*)d_in[3];
    const float* ppb     = (const float*)d_in[4];
    const float* paw     = (const float*)d_in[5];
    const float* pab     = (const float*)d_in[6];
    const float* dw1_w   = (const float*)d_in[7];
    const float* dw1_bu  = (const float*)d_in[8];
    const float* dw1_ba  = (const float*)d_in[9];
    const float* cc1_w   = (const float*)d_in[10];
    const float* cc1_bu  = (const float*)d_in[11];
    const float* cc1_ba  = (const float*)d_in[12];
    const float* dw2_w   = (const float*)d_in[13];
    const float* dw2_bu  = (const float*)d_in[14];
    const float* dw2_ba  = (const float*)d_in[15];
    const float* cc2_w   = (const float*)d_in[16];
    const float* cc2_bu  = (const float*)d_in[17];
    const float* cc2_ba  = (const float*)d_in[18];
    const float* cls_w   = (const float*)d_in[19];
    const float* cls_bu  = (const float*)d_in[20];
    const float* cls_ba  = (const float*)d_in[21];
    float* out = (float*)d_out;

    float *p1,*a1,*p2,*a2,*p3,*a3,*p4,*a4,*p5,*a5;
    cudaGetSymbolAddress((void**)&p1, g_pose1);
    cudaGetSymbolAddress((void**)&a1, g_a1);
    cudaGetSymbolAddress((void**)&p2, g_pose2);
    cudaGetSymbolAddress((void**)&a2, g_a2);
    cudaGetSymbolAddress((void**)&p3, g_pose3);
    cudaGetSymbolAddress((void**)&a3, g_a3);
    cudaGetSymbolAddress((void**)&p4, g_pose4);
    cudaGetSymbolAddress((void**)&a4, g_a4);
    cudaGetSymbolAddress((void**)&p5, g_pose5);
    cudaGetSymbolAddress((void**)&a5, g_a5);

    {   const int smem_bytes = CP_SMEM_FLOATS * 4;
        cudaFuncSetAttribute(convprim_kernel,
                             cudaFuncAttributeMaxDynamicSharedMemorySize, smem_bytes);
        convprim_kernel<<<NB*15, 256, smem_bytes>>>(
            x, conv1_w, conv1_b, ppw, ppb, paw, pab);
    }
    {   // dw1: K=7 pad=3 HIN=30 -> HINP=36, IROWS=21, PLANE=756
        constexpr int PLANE = 21*36;
        constexpr int WSOFF = ((17*PLANE) + 1) & ~1;
        const int smem_bytes = (WSOFF + 49*16 + 120) * 4;
        cudaFuncSetAttribute(dw_half_kernel<7,3,H1,H2,B1,8,256>,
                             cudaFuncAttributeMaxDynamicSharedMemorySize, smem_bytes);
        int grid = NB*B1*2;
        dw_half_kernel<7,3,H1,H2,B1,8,256><<<grid, 256, smem_bytes>>>(
            p1, a1, dw1_w, dw1_bu, dw1_ba, p2, a2); }
    {   int npos = NB*H2*H2;                 // 7200
        cc_warp_kernel<CC1_IN, 4><<<(npos+3)/4, 128>>>(
            p2, a2, cc1_w, cc1_bu, cc1_ba, p3, a3, npos); }
    {   // dw2: K=5 pad=2 HIN=15 -> HINP=19, IROWS=19, PLANE=361
        constexpr int PLANE = 19*19;
        constexpr int WSOFF = ((17*PLANE) + 1) & ~1;
        const int smem_bytes = (WSOFF + 25*16 + 4*64) * 4;
        cudaFuncSetAttribute(dw_quarter_kernel<5,2,H2,H3,CC1_OUT,8,256>,
                             cudaFuncAttributeMaxDynamicSharedMemorySize, smem_bytes);
        int grid = NB*CC1_OUT*1;
        dw_quarter_kernel<5,2,H2,H3,CC1_OUT,8,256><<<grid, 256, smem_bytes>>>(
            p3, a3, dw2_w, dw2_bu, dw2_ba, p4, a4); }
    {   int npos = NB*H3*H3;                 // 2048
        cc_warp_kernel<CC2_IN, 4><<<(npos+3)/4, 128>>>(
            p4, a4, cc2_w, cc2_bu, cc2_ba, p5, a5, npos); }
    {
        cls_vred2_kernel<<<NB*CLS_E*2, 256>>>(cls_w);
        cls_estep2_kernel<<<NB*4, 256>>>(cls_bu, cls_ba);
        cls_mstep2_kernel<<<NB*CLS_E*2, 256>>>();
        cls_estep2_kernel<<<NB*4, 256>>>(cls_bu, cls_ba);
        cls_redfin_last_kernel<<<NB*CLS_E, 256>>>(cls_bu, cls_ba, out);
    }
}

// round 14
// speedup vs baseline: 1.6295x; 1.6295x over previous
#include <cuda_runtime.h>
#include <cuda_bf16.h>

#define EPSF 1e-8f
#define LAMBDAF 1e-3f
#define LN2PI_HALF_F 0.91893853320467274178f

typedef unsigned long long u64;
typedef unsigned int u32;
__device__ __forceinline__ u64 f2pk(float lo, float hi){
    u64 r; asm("mov.b64 %0,{%1,%2};" : "=l"(r) : "f"(lo), "f"(hi)); return r;
}
__device__ __forceinline__ void f2up(u64 v, float& lo, float& hi){
    asm("mov.b64 {%0,%1},%2;" : "=f"(lo), "=f"(hi) : "l"(v));
}
__device__ __forceinline__ u64 ffma2(u64 a, u64 b, u64 c){
    u64 d; asm("fma.rn.f32x2 %0,%1,%2,%3;" : "=l"(d) : "l"(a), "l"(b), "l"(c)); return d;
}
__device__ __forceinline__ u64 fmul2(u64 a, u64 b){
    u64 d; asm("mul.rn.f32x2 %0,%1,%2;" : "=l"(d) : "l"(a), "l"(b)); return d;
}

// ---------------- network dims ----------------
#define NB 32
#define H0 64
#define H1 30
#define C1 64
#define B1 8
#define PS 16
#define H2 15
#define CC1_IN 8
#define CC1_OUT 16
#define H3 8
#define CC2_IN 16
#define CC2_OUT 16
#define CLS_D 16
#define CLS_E 10
#define CLS_BIN (H3*H3*CLS_D)   // 1024

// ---------------- scratch ----------------
__device__ float g_pose1[NB*H1*H1*B1*PS];
__device__ float g_a1   [NB*H1*H1*B1];
__device__ float g_pose2[NB*H2*H2*B1*PS];
__device__ float g_a2   [NB*H2*H2*B1];
__device__ float g_pose3[NB*H2*H2*CC1_OUT*PS];
__device__ float g_a3   [NB*H2*H2*CC1_OUT];
__device__ float g_pose4[NB*H3*H3*CC1_OUT*PS];
__device__ float g_a4   [NB*H3*H3*CC1_OUT];
__device__ float g_pose5[NB*H3*H3*CC2_OUT*PS];
__device__ float g_a5   [NB*H3*H3*CC2_OUT];
__device__ float g_votes[NB*CLS_E*CLS_BIN*PS];
__device__ float g_r    [NB*CLS_E*CLS_BIN];
__device__ float g_S    [NB*CLS_E*2*33];
__device__ float g_mu   [NB*CLS_E*16];
__device__ float g_i2   [NB*CLS_E*16];
__device__ float g_cst  [NB*CLS_E];

__device__ __forceinline__ float sigmoidf_(float x){ return 1.0f/(1.0f+expf(-x)); }

// ---------------- 1+2 fused: conv stem + relu + primary caps (f32x2) ----------------
#define CP_SMEM_FLOATS (448 + 3900 + 1600 + 8192 + 512 + 128 + 8 + 64)
__global__ void __launch_bounds__(256) convprim_kernel(
    const float* __restrict__ x,  const float* __restrict__ wc,
    const float* __restrict__ bc,
    const float* __restrict__ Wp, const float* __restrict__ bp,
    const float* __restrict__ Wa, const float* __restrict__ ba)
{
    extern __shared__ float sm[];
    float* sx  = sm;
    float* sy  = sx  + 448;
    float* swc = sy  + 3900;
    float* sWp = swc + 1600;
    float* sWa = sWp + 8192;
    float* sbp = sWa + 512;
    float* sba = sbp + 128;
    float* sbc = sba + 8;

    int tid = threadIdx.x;
    int blk = blockIdx.x;
    int ry = blk % 15, b = blk / 15;

    for (int i=tid;i<1600;i+=256) swc[i]=wc[i];
    for (int i=tid;i<8192;i+=256) sWp[i]=Wp[i];
    for (int i=tid;i<512; i+=256) sWa[i]=Wa[i];
    if (tid<128) sbp[tid]=bp[tid];
    if (tid<8)   sba[tid]=ba[tid];
    if (tid<64)  sbc[tid]=bc[tid];
    const float* xb = x + (size_t)b*H0*H0;
    for (int i=tid;i<7*64;i+=256){
        int r=i>>6, cx=i&63;
        sx[i] = xb[(4*ry+r)*H0 + cx];
    }
    __syncthreads();

    for (int i=tid;i<60*16;i+=256){
        int c4 = (i & 15)*4, pos = i >> 4;
        int oy_l = pos/30, ox = pos%30;
        u64 a0 = f2pk(sbc[c4],   sbc[c4+1]);
        u64 a1 = f2pk(sbc[c4+2], sbc[c4+3]);
        #pragma unroll
        for (int kh=0;kh<5;kh++){
            const float* xr = &sx[(oy_l*2+kh)*64 + ox*2];
            #pragma unroll
            for (int kw=0;kw<5;kw++){
                float xv = xr[kw];
                u64 x2 = f2pk(xv,xv);
                const u64* w2 = (const u64*)&swc[(kh*5+kw)*64 + c4];
                a0 = ffma2(x2, w2[0], a0);
                a1 = ffma2(x2, w2[1], a1);
            }
        }
        float v0,v1,v2,v3;
        f2up(a0,v0,v1); f2up(a1,v2,v3);
        float* yo = &sy[pos*65 + c4];
        yo[0]=fmaxf(v0,0.f); yo[1]=fmaxf(v1,0.f);
        yo[2]=fmaxf(v2,0.f); yo[3]=fmaxf(v3,0.f);
    }
    __syncthreads();

    for (int i=tid;i<60*34;i+=256){
        int qd = i % 34, pos = i / 34;
        int oy = ry*2 + pos/30, ox = pos%30;
        size_t pg = ((size_t)(b*H1+oy))*H1 + ox;
        const float* yy = &sy[pos*65];
        if (qd < 32){
            int d0 = qd*4;
            u64 a0 = f2pk(sbp[d0],   sbp[d0+1]);
            u64 a1 = f2pk(sbp[d0+2], sbp[d0+3]);
            #pragma unroll 8
            for (int c=0;c<64;c++){
                float yv = yy[c];
                u64 y2 = f2pk(yv,yv);
                const u64* w2 = (const u64*)&sWp[c*128 + d0];
                a0 = ffma2(y2, w2[0], a0);
                a1 = ffma2(y2, w2[1], a1);
            }
            float v0,v1,v2,v3;
            f2up(a0,v0,v1); f2up(a1,v2,v3);
            float4 o4; o4.x=v0; o4.y=v1; o4.z=v2; o4.w=v3;
            *(float4*)&g_pose1[pg*128 + d0] = o4;
        } else {
            int da0 = (qd-32)*4;
            u64 a0 = f2pk(sba[da0],   sba[da0+1]);
            u64 a1 = f2pk(sba[da0+2], sba[da0+3]);
            #pragma unroll 8
            for (int c=0;c<64;c++){
                float yv = yy[c];
                u64 y2 = f2pk(yv,yv);
                const u64* w2 = (const u64*)&sWa[c*8 + da0];
                a0 = ffma2(y2, w2[0], a0);
                a1 = ffma2(y2, w2[1], a1);
            }
            float v0,v1,v2,v3;
            f2up(a0,v0,v1); f2up(a1,v2,v3);
            float4 o4;
            o4.x=sigmoidf_(v0); o4.y=sigmoidf_(v1);
            o4.z=sigmoidf_(v2); o4.w=sigmoidf_(v3);
            *(float4*)&g_a1[pg*8 + da0] = o4;
        }
    }
}

// ---------------- dw caps HALF-split (dw1) ----------------
template<int K, int PAD, int HIN, int HOUT, int BC, int OYT, int BLK>
__global__ void __launch_bounds__(BLK) dw_half_kernel(
    const float* __restrict__ pose_in,
    const float* __restrict__ a_in_g,
    const float* __restrict__ W,
    const float* __restrict__ bu, const float* __restrict__ ba,
    float* __restrict__ pose_out,
    float* __restrict__ a_out_g)
{
    constexpr int NT    = (HOUT + OYT - 1)/OYT;
    constexpr int IROWS = (OYT-1)*2 + K;
    constexpr int PLANE = IROWS*HIN;
    constexpr int NPOS  = OYT*HOUT;
    __shared__ float ps[16][PLANE];
    __shared__ float as[PLANE];
    __shared__ __align__(16) float ws[K*K*16];
    __shared__ float s_h[NPOS];

    int blk = blockIdx.x;
    int tile = blk % NT;
    int c    = (blk / NT) % BC;
    int b    = blk / (NT*BC);
    int oy0  = tile*OYT;
    int iy0  = oy0*2 - PAD;
    int tid  = threadIdx.x;

    for (int i=tid; i<K*K*16; i+=BLK)
        ws[i] = W[(i>>4)*(BC*16) + c*16 + (i&15)];

    const float4* pbase = (const float4*)pose_in;
    for (int i=tid; i<PLANE*4; i+=BLK){
        int q4 = i & 3;
        int pos = i >> 2;
        int r = pos / HIN, ix = pos % HIN;
        int iy = iy0 + r;
        float4 v = make_float4(0.f,0.f,0.f,0.f);
        bool ok = (iy >= 0 && iy < HIN);
        if (ok)
            v = pbase[((size_t)((b*HIN+iy)*HIN+ix))*(BC*4) + c*4 + q4];
        ps[q4*4+0][pos]=v.x; ps[q4*4+1][pos]=v.y;
        ps[q4*4+2][pos]=v.z; ps[q4*4+3][pos]=v.w;
        if (q4 == 0)
            as[pos] = ok ? a_in_g[((b*HIN+iy)*HIN+ix)*BC + c] : 0.0f;
    }
    __syncthreads();

    bool act = tid < 2*NPOS;
    int half = 0, pos_t = 0, oy = 0, ox = 0;
    if (act){
        half  = (tid >= NPOS) ? 1 : 0;
        pos_t = tid - half*NPOS;
        int oy_l = pos_t / HOUT;
        ox = pos_t % HOUT;
        oy = oy0 + oy_l;
        if (oy >= HOUT) act = false;
    }

    float S0 = 0.0f;
    u64 T1p[4], T2p[4];
    #pragma unroll
    for (int a=0;a<4;a++){ T1p[a]=f2pk(0.f,0.f); T2p[a]=f2pk(0.f,0.f); }

    if (act){
        #pragma unroll
        for (int ki=0; ki<K; ki++){
            int iy = oy*2 + ki - PAD;
            if (iy < 0 || iy >= HIN) continue;
            int rr = iy - iy0;
            #pragma unroll
            for (int kj=0; kj<K; kj++){
                int ix = ox*2 + kj - PAD;
                if (ix < 0 || ix >= HIN) continue;
                int sp = rr*HIN + ix;
                float w = as[sp];
                S0 += w;
                u64 wp = f2pk(w,w);
                const u64* wk2 = (const u64*)&ws[(ki*K+kj)*16];
                #pragma unroll
                for (int ii=0; ii<2; ii++){
                    int irow = half*2 + ii;
                    u64 pm2[4];
                    #pragma unroll
                    for (int j=0;j<4;j++){
                        float pj = ps[irow*4+j][sp];
                        pm2[j] = f2pk(pj,pj);
                    }
                    #pragma unroll
                    for (int l2=0;l2<2;l2++){
                        u64 vv = f2pk(0.f,0.f);
                        #pragma unroll
                        for (int j=0;j<4;j++)
                            vv = ffma2(pm2[j], wk2[j*2+l2], vv);
                        int a = ii*2 + l2;
                        T1p[a] = ffma2(wp, vv, T1p[a]);
                        T2p[a] = ffma2(fmul2(wp, vv), vv, T2p[a]);
                    }
                }
            }
        }
    }

    float hls_own = 0.0f;
    if (act){
        float inv = 1.0f/(S0 + EPSF);
        float mu[8];
        #pragma unroll
        for (int a=0;a<4;a++){
            float t1l,t1h,t2l,t2h;
            f2up(T1p[a],t1l,t1h); f2up(T2p[a],t2l,t2h);
            int ii = a>>1, l2 = a&1;
            int q0 = ii*4 + l2*2;
            float m0 = t1l*inv;
            float m1 = t1h*inv;
            mu[q0]   = m0;
            mu[q0+1] = m1;
            float sg0 = fmaxf((t2l - 2.0f*m0*t1l + m0*m0*S0)*inv, 0.0f) + EPSF;
            float sg1 = fmaxf((t2h - 2.0f*m1*t1h + m1*m1*S0)*inv, 0.0f) + EPSF;
            hls_own += 0.5f*logf(sg0*sg1);
        }
        size_t o = (size_t)((b*HOUT+oy)*HOUT+ox);
        float4* po = (float4*)&pose_out[o*(BC*16) + c*16 + half*8];
        float4 v4;
        v4.x=mu[0]; v4.y=mu[1]; v4.z=mu[2]; v4.w=mu[3]; po[0]=v4;
        v4.x=mu[4]; v4.y=mu[5]; v4.z=mu[6]; v4.w=mu[7]; po[1]=v4;
        if (half) s_h[pos_t] = hls_own;
    }
    __syncthreads();
    if (act && half == 0){
        float hls = hls_own + s_h[pos_t];
        float cost = (hls + 16.0f*bu[0]) * S0;
        float ao = sigmoidf_(LAMBDAF*(ba[0] - cost));
        size_t o = (size_t)((b*HOUT+oy)*HOUT+ox);
        a_out_g[o*BC + c] = ao;
    }
}

// ---------------- dw caps QUARTER-split (dw2) ----------------
template<int K, int PAD, int HIN, int HOUT, int BC, int OYT, int BLK>
__global__ void __launch_bounds__(BLK) dw_quarter_kernel(
    const float* __restrict__ pose_in,
    const float* __restrict__ a_in_g,
    const float* __restrict__ W,
    const float* __restrict__ bu, const float* __restrict__ ba,
    float* __restrict__ pose_out,
    float* __restrict__ a_out_g)
{
    constexpr int NT    = (HOUT + OYT - 1)/OYT;
    constexpr int IROWS = (OYT-1)*2 + K;
    constexpr int PLANE = IROWS*HIN;
    constexpr int NPOS  = OYT*HOUT;
    __shared__ float ps[16][PLANE];
    __shared__ float as[PLANE];
    __shared__ __align__(16) float ws[K*K*16];
    __shared__ float s_h[4][NPOS];

    int blk = blockIdx.x;
    int tile = blk % NT;
    int c    = (blk / NT) % BC;
    int b    = blk / (NT*BC);
    int oy0  = tile*OYT;
    int iy0  = oy0*2 - PAD;
    int tid  = threadIdx.x;

    for (int i=tid; i<K*K*16; i+=BLK)
        ws[i] = W[(i>>4)*(BC*16) + c*16 + (i&15)];

    const float4* pbase = (const float4*)pose_in;
    for (int i=tid; i<PLANE*4; i+=BLK){
        int q4 = i & 3;
        int pos = i >> 2;
        int r = pos / HIN, ix = pos % HIN;
        int iy = iy0 + r;
        float4 v = make_float4(0.f,0.f,0.f,0.f);
        bool ok = (iy >= 0 && iy < HIN);
        if (ok)
            v = pbase[((size_t)((b*HIN+iy)*HIN+ix))*(BC*4) + c*4 + q4];
        ps[q4*4+0][pos]=v.x; ps[q4*4+1][pos]=v.y;
        ps[q4*4+2][pos]=v.z; ps[q4*4+3][pos]=v.w;
        if (q4 == 0)
            as[pos] = ok ? a_in_g[((b*HIN+iy)*HIN+ix)*BC + c] : 0.0f;
    }
    __syncthreads();

    bool act = tid < 4*NPOS;
    int quarter = 0, pos_t = 0, oy = 0, ox = 0;
    if (act){
        quarter = tid / NPOS;
        pos_t   = tid - quarter*NPOS;
        int oy_l = pos_t / HOUT;
        ox = pos_t % HOUT;
        oy = oy0 + oy_l;
        if (oy >= HOUT) act = false;
    }

    float S0 = 0.0f;
    u64 T1p[2], T2p[2];
    T1p[0]=f2pk(0.f,0.f); T1p[1]=f2pk(0.f,0.f);
    T2p[0]=f2pk(0.f,0.f); T2p[1]=f2pk(0.f,0.f);

    if (act){
        #pragma unroll
        for (int ki=0; ki<K; ki++){
            int iy = oy*2 + ki - PAD;
            if (iy < 0 || iy >= HIN) continue;
            int rr = iy - iy0;
            #pragma unroll
            for (int kj=0; kj<K; kj++){
                int ix = ox*2 + kj - PAD;
                if (ix < 0 || ix >= HIN) continue;
                int sp = rr*HIN + ix;
                float w = as[sp];
                S0 += w;
                u64 wp = f2pk(w,w);
                const u64* wk2 = (const u64*)&ws[(ki*K+kj)*16];
                u64 pm2[4];
                #pragma unroll
                for (int j=0;j<4;j++){
                    float pj = ps[quarter*4+j][sp];
                    pm2[j] = f2pk(pj,pj);
                }
                #pragma unroll
                for (int l2=0;l2<2;l2++){
                    u64 vv = f2pk(0.f,0.f);
                    #pragma unroll
                    for (int j=0;j<4;j++)
                        vv = ffma2(pm2[j], wk2[j*2+l2], vv);
                    T1p[l2] = ffma2(wp, vv, T1p[l2]);
                    T2p[l2] = ffma2(fmul2(wp, vv), vv, T2p[l2]);
                }
            }
        }
    }

    float hls_own = 0.0f;
    if (act){
        float inv = 1.0f/(S0 + EPSF);
        float mu[4];
        float sgp = 1.0f;
        #pragma unroll
        for (int l2=0;l2<2;l2++){
            float t1l,t1h,t2l,t2h;
            f2up(T1p[l2],t1l,t1h); f2up(T2p[l2],t2l,t2h);
            float m0 = t1l*inv;
            float m1 = t1h*inv;
            mu[l2*2]   = m0;
            mu[l2*2+1] = m1;
            float sg0 = fmaxf((t2l - 2.0f*m0*t1l + m0*m0*S0)*inv, 0.0f) + EPSF;
            float sg1 = fmaxf((t2h - 2.0f*m1*t1h + m1*m1*S0)*inv, 0.0f) + EPSF;
            sgp *= sg0*sg1;
        }
        hls_own = 0.5f*logf(sgp);
        size_t o = (size_t)((b*HOUT+oy)*HOUT+ox);
        float4 v4; v4.x=mu[0]; v4.y=mu[1]; v4.z=mu[2]; v4.w=mu[3];
        *(float4*)&pose_out[o*(BC*16) + c*16 + quarter*4] = v4;
        s_h[quarter][pos_t] = hls_own;
    }
    __syncthreads();
    if (act && quarter == 0){
        float hls = hls_own + s_h[1][pos_t] + s_h[2][pos_t] + s_h[3][pos_t];
        float cost = (hls + 16.0f*bu[0]) * S0;
        float ao = sigmoidf_(LAMBDAF*(ba[0] - cost));
        size_t o = (size_t)((b*HOUT+oy)*HOUT+ox);
        a_out_g[o*BC + c] = ao;
    }
}

// ---------------- 1x1 conv caps: warp-per-position, float4-vectorized smem votes ----------------
template<int BIN, int WPB>
__global__ void __launch_bounds__(WPB*32) cc_warp_kernel(
    const float* __restrict__ pose_in,
    const float* __restrict__ a_g,
    const float* __restrict__ W,
    const float* __restrict__ bu, const float* __restrict__ ba,
    float* __restrict__ pose_out,
    float* __restrict__ a_out_g,
    int npos)
{
    __shared__ float sW[BIN*256];
    __shared__ float4 sv[WPB][BIN*2*32];
    __shared__ float s_ln[WPB][BIN*17];
    __shared__ float s_rw[WPB][BIN*17];
    __shared__ float s_ain[WPB][BIN];

    int tid = threadIdx.x;
    for (int i=tid; i<BIN*256; i+=WPB*32){
        int c2 = i & 15; int rest = i >> 4;
        int l = rest & 3; int j = (rest>>2)&3; int bin = rest>>4;
        sW[i] = W[(((size_t)bin*16 + c2)*4 + j)*4 + l];
    }
    __syncthreads();

    int warp = tid >> 5, lane = tid & 31;
    int pos = blockIdx.x*WPB + warp;
    if (pos >= npos) return;
    int c = lane & 15, half = lane >> 4;
    float4* v  = sv[warp];
    float* lnp = s_ln[warp];
    float* rwp = s_rw[warp];
    float* ain = s_ain[warp];

    const float* pm = pose_in + (size_t)pos*BIN*16;
    const float* ag = a_g + (size_t)pos*BIN;
    if (half == 0 && c < BIN) ain[c] = ag[c];

    float T1[8], T2[8]; float S0 = 0.0f;
    #pragma unroll
    for (int q=0;q<8;q++){ T1[q]=0.0f; T2[q]=0.0f; }

    #pragma unroll
    for (int bin=0; bin<BIN; bin++){
        float w = ag[bin] * (1.0f/16.0f);
        S0 += w;
        const float4* pm4 = (const float4*)(pm + bin*16 + half*8);
        float4 p0 = pm4[0], p1 = pm4[1];
        float pmr[8] = {p0.x,p0.y,p0.z,p0.w,p1.x,p1.y,p1.z,p1.w};
        float sq[8];
        #pragma unroll
        for (int q=0;q<8;q++){
            int i0 = q>>2, l = q&3;
            float s = 0.0f;
            #pragma unroll
            for (int j=0;j<4;j++)
                s += pmr[i0*4+j] * sW[(((bin*4+j)*4+l)<<4) + c];
            sq[q] = s;
            T1[q] += w*s;
            T2[q] += w*s*s;
        }
        float4 v4a; v4a.x=sq[0]; v4a.y=sq[1]; v4a.z=sq[2]; v4a.w=sq[3];
        float4 v4b; v4b.x=sq[4]; v4b.y=sq[5]; v4b.z=sq[6]; v4b.w=sq[7];
        v[(bin*2+0)*32 + lane] = v4a;
        v[(bin*2+1)*32 + lane] = v4b;
    }

    float buC = bu[c], baC = ba[c];
    float mu[8], i2[8], cst = 0.0f, ao = 0.0f;
    {
        float inv = 1.0f/(S0 + EPSF);
        float sgp01 = 1.0f, sgp23 = 1.0f;
        #pragma unroll
        for (int q=0;q<8;q++){
            float m = T1[q]*inv;
            mu[q] = m;
            float sg = fmaxf(T2[q]*inv - m*m, 0.0f) + EPSF;
            i2[q] = 0.5f/sg;
            if (q < 4) sgp01 *= sg; else sgp23 *= sg;
        }
        float hls = 0.5f*(logf(sgp01) + logf(sgp23));
        hls += __shfl_xor_sync(0xffffffffu, hls, 16);
        float cost = (hls + 16.0f*buC) * S0;
        ao = sigmoidf_(LAMBDAF*(baC - cost));
        cst = -hls - 16.0f*LN2PI_HALF_F + logf(EPSF + ao);
    }

    #pragma unroll
    for (int it=0; it<2; it++){
        float part[BIN];
        #pragma unroll
        for (int bin=0;bin<BIN;bin++){
            float4 va = v[(bin*2+0)*32 + lane];
            float4 vb = v[(bin*2+1)*32 + lane];
            float d0=va.x-mu[0], d1=va.y-mu[1], d2=va.z-mu[2], d3=va.w-mu[3];
            float d4=vb.x-mu[4], d5=vb.y-mu[5], d6=vb.z-mu[6], d7=vb.w-mu[7];
            part[bin] = -(d0*d0*i2[0]+d1*d1*i2[1]+d2*d2*i2[2]+d3*d3*i2[3]
                        + d4*d4*i2[4]+d5*d5*i2[5]+d6*d6*i2[6]+d7*d7*i2[7]);
        }
        #pragma unroll
        for (int bin=0;bin<BIN;bin++)
            part[bin] += __shfl_xor_sync(0xffffffffu, part[bin], 16);
        if (half == 0){
            #pragma unroll
            for (int bin=0;bin<BIN;bin++)
                lnp[bin*17 + c] = part[bin] + cst;
        }
        __syncwarp();
        if (lane < BIN){
            float l16[16];
            float mx = -1e30f;
            #pragma unroll
            for (int c2=0;c2<16;c2++){ l16[c2] = lnp[lane*17 + c2]; mx = fmaxf(mx, l16[c2]); }
            float sum = 0.0f;
            #pragma unroll
            for (int c2=0;c2<16;c2++){ l16[c2] = expf(l16[c2]-mx); sum += l16[c2]; }
            float f = ain[lane]/sum;
            #pragma unroll
            for (int c2=0;c2<16;c2++) rwp[lane*17 + c2] = l16[c2]*f;
        }
        __syncwarp();
        float nT1[8], nT2[8]; float nS0 = 0.0f;
        #pragma unroll
        for (int q=0;q<8;q++){ nT1[q]=0.0f; nT2[q]=0.0f; }
        #pragma unroll
        for (int bin=0;bin<BIN;bin++){
            float w = rwp[bin*17 + c];
            nS0 += w;
            float4 va = v[(bin*2+0)*32 + lane];
            float4 vb = v[(bin*2+1)*32 + lane];
            nT1[0]+=w*va.x; nT2[0]+=w*va.x*va.x;
            nT1[1]+=w*va.y; nT2[1]+=w*va.y*va.y;
            nT1[2]+=w*va.z; nT2[2]+=w*va.z*va.z;
            nT1[3]+=w*va.w; nT2[3]+=w*va.w*va.w;
            nT1[4]+=w*vb.x; nT2[4]+=w*vb.x*vb.x;
            nT1[5]+=w*vb.y; nT2[5]+=w*vb.y*vb.y;
            nT1[6]+=w*vb.z; nT2[6]+=w*vb.z*vb.z;
            nT1[7]+=w*vb.w; nT2[7]+=w*vb.w*vb.w;
        }
        float inv = 1.0f/(nS0 + EPSF);
        float sgp01 = 1.0f, sgp23 = 1.0f;
        #pragma unroll
        for (int q=0;q<8;q++){
            float m = nT1[q]*inv;
            mu[q] = m;
            float sg = fmaxf(nT2[q]*inv - m*m, 0.0f) + EPSF;
            i2[q] = 0.5f/sg;
            if (q < 4) sgp01 *= sg; else sgp23 *= sg;
        }
        float hls = 0.5f*(logf(sgp01) + logf(sgp23));
        hls += __shfl_xor_sync(0xffffffffu, hls, 16);
        float cost = (hls + 16.0f*buC) * nS0;
        ao = sigmoidf_(LAMBDAF*(baC - cost));
        if (it == 0) cst = -hls - 16.0f*LN2PI_HALF_F + logf(EPSF + ao);
    }

    size_t ob = (size_t)pos*256 + c*16 + half*8;
    #pragma unroll
    for (int q=0;q<8;q++) pose_out[ob+q] = mu[q];
    if (half == 0) a_out_g[(size_t)pos*16 + c] = ao;
}

// ---------------- cls iter0: votes + split partial sums (grid NB*CLS_E*2) ----------------
__global__ void __launch_bounds__(256) cls_vred2_kernel(const float* __restrict__ W)
{
    int be2 = blockIdx.x;
    int halfb = be2 & 1;
    int be = be2 >> 1;
    int b = be / CLS_E, e = be % CLS_E;
    int tid = threadIdx.x, lane = tid & 31, warp = tid >> 5;

    __shared__ float sw[16*17];
    if (tid < 256){
        int d = tid >> 4, p = tid & 15;
        int j = p >> 2, l = p & 3;
        sw[d*17 + p] = W[((d*CLS_E + e)*4 + j)*4 + l];
    }
    __syncthreads();

    float s0 = 0.0f, s1[16], s2[16];
    #pragma unroll
    for (int q=0;q<16;q++){ s1[q]=0.0f; s2[q]=0.0f; }

    int bin0 = halfb*512;
    for (int bin=bin0+tid; bin<bin0+512; bin+=256){
        int d  = bin & 15;
        int ww = (bin >> 4) & 7;
        int hh = bin >> 7;
        const float4* pm4 = (const float4*)(g_pose5 + ((size_t)b*CLS_BIN + bin)*16);
        float4 P0 = pm4[0], P1 = pm4[1], P2 = pm4[2], P3 = pm4[3];
        float pmv[16] = {P0.x,P0.y,P0.z,P0.w, P1.x,P1.y,P1.z,P1.w,
                         P2.x,P2.y,P2.z,P2.w, P3.x,P3.y,P3.z,P3.w};
        float w = 0.1f * g_a5[(size_t)b*CLS_BIN + bin];
        s0 += w;
        float4* vout = (float4*)(g_votes + ((size_t)be*CLS_BIN + bin)*16);
        const float* swd = &sw[d*17];
        #pragma unroll
        for (int i=0;i<4;i++){
            float vv[4];
            #pragma unroll
            for (int l=0;l<4;l++){
                float s = 0.0f;
                #pragma unroll
                for (int j=0;j<4;j++) s += pmv[i*4+j]*swd[j*4+l];
                vv[l] = s;
            }
            if (i == 0){ vv[0] += (float)hh*0.125f; vv[1] += (float)ww*0.125f; }
            float4 o4; o4.x=vv[0]; o4.y=vv[1]; o4.z=vv[2]; o4.w=vv[3];
            vout[i] = o4;
            #pragma unroll
            for (int l=0;l<4;l++){
                s1[i*4+l] += w*vv[l];
                s2[i*4+l] += w*vv[l]*vv[l];
            }
        }
    }

    #pragma unroll
    for (int off=16; off; off>>=1){
        s0 += __shfl_xor_sync(0xffffffffu, s0, off);
        #pragma unroll
        for (int q=0;q<16;q++){
            s1[q] += __shfl_xor_sync(0xffffffffu, s1[q], off);
            s2[q] += __shfl_xor_sync(0xffffffffu, s2[q], off);
        }
    }
    __shared__ float red[8][33];
    if (lane == 0){
        red[warp][0] = s0;
        #pragma unroll
        for (int q=0;q<16;q++){ red[warp][1+q]=s1[q]; red[warp][17+q]=s2[q]; }
    }
    __syncthreads();
    if (tid < 33){
        float t = 0.0f;
        #pragma unroll
        for (int w8=0;w8<8;w8++) t += red[w8][tid];
        g_S[((size_t)be*2 + halfb)*33 + tid] = t;
    }
}

// ---------------- cls M-step: split partial sums from stored votes+r ----------------
__global__ void __launch_bounds__(256) cls_mstep2_kernel()
{
    int be2 = blockIdx.x;
    int halfb = be2 & 1;
    int be = be2 >> 1;
    int b = be / CLS_E;
    const float* vb = g_votes + (size_t)be*CLS_BIN*16;
    const float* rr = g_r + (size_t)be*CLS_BIN;
    const float* ab = g_a5 + (size_t)b*CLS_BIN;
    int tid = threadIdx.x, lane = tid & 31, warp = tid >> 5;

    float s0 = 0.0f, s1[16], s2[16];
    #pragma unroll
    for (int q=0;q<16;q++){ s1[q]=0.0f; s2[q]=0.0f; }

    int bin0 = halfb*512;
    for (int bin=bin0+tid; bin<bin0+512; bin+=256){
        float w = rr[bin] * ab[bin];
        s0 += w;
        const float4* vv = (const float4*)(vb + (size_t)bin*16);
        #pragma unroll
        for (int q4=0;q4<4;q4++){
            float4 v4 = vv[q4];
            s1[q4*4+0] += w*v4.x; s2[q4*4+0] += w*v4.x*v4.x;
            s1[q4*4+1] += w*v4.y; s2[q4*4+1] += w*v4.y*v4.y;
            s1[q4*4+2] += w*v4.z; s2[q4*4+2] += w*v4.z*v4.z;
            s1[q4*4+3] += w*v4.w; s2[q4*4+3] += w*v4.w*v4.w;
        }
    }
    #pragma unroll
    for (int off=16; off; off>>=1){
        s0 += __shfl_xor_sync(0xffffffffu, s0, off);
        #pragma unroll
        for (int q=0;q<16;q++){
            s1[q] += __shfl_xor_sync(0xffffffffu, s1[q], off);
            s2[q] += __shfl_xor_sync(0xffffffffu, s2[q], off);
        }
    }
    __shared__ float red[8][33];
    if (lane == 0){
        red[warp][0] = s0;
        #pragma unroll
        for (int q=0;q<16;q++){ red[warp][1+q]=s1[q]; red[warp][17+q]=s2[q]; }
    }
    __syncthreads();
    if (tid < 33){
        float t = 0.0f;
        #pragma unroll
        for (int w8=0;w8<8;w8++) t += red[w8][tid];
        g_S[((size_t)be*2 + halfb)*33 + tid] = t;
    }
}

// ---------------- cls E-step: finalize-in-preamble + softmax (grid NB*4) ----------------
__global__ void __launch_bounds__(256) cls_estep2_kernel(
    const float* __restrict__ bu, const float* __restrict__ ba)
{
    __shared__ float s_mu[CLS_E*16];
    __shared__ float s_i2[CLS_E*16];
    __shared__ float s_cst[CLS_E];

    int tid = threadIdx.x;
    int b = blockIdx.x >> 2;
    int bin = ((blockIdx.x & 3) << 8) + tid;

    if (tid < 160){
        int e = tid >> 4, q = tid & 15;
        size_t base = ((size_t)(b*CLS_E + e))*66;
        float S0 = g_S[base] + g_S[base+33];
        float S1 = g_S[base+1+q]  + g_S[base+34+q];
        float S2 = g_S[base+17+q] + g_S[base+50+q];
        float inv = 1.0f/(S0 + EPSF);
        float m = S1*inv;
        float sg = fmaxf((S2 - 2.0f*m*S1 + m*m*S0)*inv, 0.0f) + EPSF;
        s_mu[tid] = m;
        s_i2[tid] = 0.5f/sg;
        float hl = 0.5f*logf(sg);
        #pragma unroll
        for (int off=8; off; off>>=1)
            hl += __shfl_xor_sync(0xffffffffu, hl, off);
        if (q == 0){
            float cost = (hl + 16.0f*bu[e]) * S0;
            float ao = sigmoidf_(LAMBDAF*(ba[e] - cost));
            s_cst[e] = -hl - 16.0f*LN2PI_HALF_F + logf(EPSF + ao);
        }
    }
    __syncthreads();

    float lnap[CLS_E];
    float mx = -1e30f;
    #pragma unroll
    for (int e=0;e<CLS_E;e++){
        int be = b*CLS_E + e;
        const float4* vv = (const float4*)(g_votes + ((size_t)be*CLS_BIN + bin)*16);
        const float4* mm = (const float4*)&s_mu[e*16];
        const float4* ii = (const float4*)&s_i2[e*16];
        float acc = 0.0f;
        #pragma unroll
        for (int q4=0;q4<4;q4++){
            float4 v4 = vv[q4], m4 = mm[q4], i4 = ii[q4];
            float d0=v4.x-m4.x, d1=v4.y-m4.y, d2=v4.z-m4.z, d3=v4.w-m4.w;
            acc -= d0*d0*i4.x + d1*d1*i4.y + d2*d2*i4.z + d3*d3*i4.w;
        }
        lnap[e] = acc + s_cst[e];
        mx = fmaxf(mx, lnap[e]);
    }
    float sum = 0.0f;
    #pragma unroll
    for (int e=0;e<CLS_E;e++){ lnap[e] = expf(lnap[e]-mx); sum += lnap[e]; }
    float isum = 1.0f/sum;
    #pragma unroll
    for (int e=0;e<CLS_E;e++)
        g_r[((size_t)(b*CLS_E+e))*CLS_BIN + bin] = lnap[e]*isum;
}

// ---------------- cls final M-step: full reduce + a_out (grid NB*CLS_E) ----------------
__global__ void __launch_bounds__(256) cls_redfin_last_kernel(
    const float* __restrict__ bu, const float* __restrict__ ba,
    float* __restrict__ out)
{
    int be = blockIdx.x;
    int b = be / CLS_E, e = be % CLS_E;
    const float* vb = g_votes + (size_t)be*CLS_BIN*16;
    const float* rr = g_r + (size_t)be*CLS_BIN;
    const float* ab = g_a5 + (size_t)b*CLS_BIN;
    int tid = threadIdx.x, lane = tid & 31, warp = tid >> 5;

    float s0 = 0.0f, s1[16], s2[16];
    #pragma unroll
    for (int q=0;q<16;q++){ s1[q]=0.0f; s2[q]=0.0f; }

    for (int bin=tid; bin<CLS_BIN; bin+=256){
        float w = rr[bin] * ab[bin];
        s0 += w;
        const float4* vv = (const float4*)(vb + (size_t)bin*16);
        #pragma unroll
        for (int q4=0;q4<4;q4++){
            float4 v4 = vv[q4];
            s1[q4*4+0] += w*v4.x; s2[q4*4+0] += w*v4.x*v4.x;
            s1[q4*4+1] += w*v4.y; s2[q4*4+1] += w*v4.y*v4.y;
            s1[q4*4+2] += w*v4.z; s2[q4*4+2] += w*v4.z*v4.z;
            s1[q4*4+3] += w*v4.w; s2[q4*4+3] += w*v4.w*v4.w;
        }
    }
    #pragma unroll
    for (int off=16; off; off>>=1){
        s0 += __shfl_xor_sync(0xffffffffu, s0, off);
        #pragma unroll
        for (int q=0;q<16;q++){
            s1[q] += __shfl_xor_sync(0xffffffffu, s1[q], off);
            s2[q] += __shfl_xor_sync(0xffffffffu, s2[q], off);
        }
    }
    __shared__ float red[8][33];
    __shared__ float smS[33];
    if (lane == 0){
        red[warp][0] = s0;
        #pragma unroll
        for (int q=0;q<16;q++){ red[warp][1+q]=s1[q]; red[warp][17+q]=s2[q]; }
    }
    __syncthreads();
    if (tid < 33){
        float t = 0.0f;
        #pragma unroll
        for (int w8=0;w8<8;w8++) t += red[w8][tid];
        smS[tid] = t;
    }
    __syncthreads();
    if (tid < 16){
        float S0 = smS[0];
        float S1 = smS[1+tid];
        float S2 = smS[17+tid];
        float inv = 1.0f/(S0 + EPSF);
        float m = S1*inv;
        float sg = fmaxf((S2 - 2.0f*m*S1 + m*m*S0)*inv, 0.0f) + EPSF;
        float hl = 0.5f*logf(sg);
        #pragma unroll
        for (int off=8; off; off>>=1)
            hl += __shfl_xor_sync(0x0000ffffu, hl, off);
        if (tid == 0){
            float cost = (hl + 16.0f*bu[e]) * S0;
            float ao = sigmoidf_(LAMBDAF*(ba[e] - cost));
            out[b*CLS_E + e] = ao;
        }
    }
}

// ---------------- launch ----------------
extern "C" void kernel_launch(void* const* d_in, const int* in_sizes, int n_in,
                              void* d_out, int out_size)
{
    const float* x       = (const float*)d_in[0];
    const float* conv1_w = (const float*)d_in[1];
    const float* conv1_b = (const float*)d_in[2];
    const float* ppw     = (const float*)d_in[3];
    const float* ppb     = (const float*)d_in[4];
    const float* paw     = (const float*)d_in[5];
    const float* pab     = (const float*)d_in[6];
    const float* dw1_w   = (const float*)d_in[7];
    const float* dw1_bu  = (const float*)d_in[8];
    const float* dw1_ba  = (const float*)d_in[9];
    const float* cc1_w   = (const float*)d_in[10];
    const float* cc1_bu  = (const float*)d_in[11];
    const float* cc1_ba  = (const float*)d_in[12];
    const float* dw2_w   = (const float*)d_in[13];
    const float* dw2_bu  = (const float*)d_in[14];
    const float* dw2_ba  = (const float*)d_in[15];
    const float* cc2_w   = (const float*)d_in[16];
    const float* cc2_bu  = (const float*)d_in[17];
    const float* cc2_ba  = (const float*)d_in[18];
    const float* cls_w   = (const float*)d_in[19];
    const float* cls_bu  = (const float*)d_in[20];
    const float* cls_ba  = (const float*)d_in[21];
    float* out = (float*)d_out;

    float *p1,*a1,*p2,*a2,*p3,*a3,*p4,*a4,*p5,*a5;
    cudaGetSymbolAddress((void**)&p1, g_pose1);
    cudaGetSymbolAddress((void**)&a1, g_a1);
    cudaGetSymbolAddress((void**)&p2, g_pose2);
    cudaGetSymbolAddress((void**)&a2, g_a2);
    cudaGetSymbolAddress((void**)&p3, g_pose3);
    cudaGetSymbolAddress((void**)&a3, g_a3);
    cudaGetSymbolAddress((void**)&p4, g_pose4);
    cudaGetSymbolAddress((void**)&a4, g_a4);
    cudaGetSymbolAddress((void**)&p5, g_pose5);
    cudaGetSymbolAddress((void**)&a5, g_a5);

    {   const int smem_bytes = CP_SMEM_FLOATS * 4;
        cudaFuncSetAttribute(convprim_kernel,
                             cudaFuncAttributeMaxDynamicSharedMemorySize, smem_bytes);
        convprim_kernel<<<NB*15, 256, smem_bytes>>>(
            x, conv1_w, conv1_b, ppw, ppb, paw, pab);
    }
    {   int grid = NB*B1*2;
        dw_half_kernel<7,3,H1,H2,B1,8,256><<<grid, 256>>>(
            p1, a1, dw1_w, dw1_bu, dw1_ba, p2, a2); }
    {   int npos = NB*H2*H2;                 // 7200
        cc_warp_kernel<CC1_IN, 4><<<(npos+3)/4, 128>>>(
            p2, a2, cc1_w, cc1_bu, cc1_ba, p3, a3, npos); }
    {   int grid = NB*CC1_OUT*1;
        dw_quarter_kernel<5,2,H2,H3,CC1_OUT,8,256><<<grid, 256>>>(
            p3, a3, dw2_w, dw2_bu, dw2_ba, p4, a4); }
    {   int npos = NB*H3*H3;                 // 2048
        cc_warp_kernel<CC2_IN, 4><<<(npos+3)/4, 128>>>(
            p4, a4, cc2_w, cc2_bu, cc2_ba, p5, a5, npos); }
    {
        cls_vred2_kernel<<<NB*CLS_E*2, 256>>>(cls_w);
        cls_estep2_kernel<<<NB*4, 256>>>(cls_bu, cls_ba);
        cls_mstep2_kernel<<<NB*CLS_E*2, 256>>>();
        cls_estep2_kernel<<<NB*4, 256>>>(cls_bu, cls_ba);
        cls_redfin_last_kernel<<<NB*CLS_E, 256>>>(cls_bu, cls_ba, out);
    }
}